// round 1
// baseline (speedup 1.0000x reference)
#include <cuda_runtime.h>
#include <math.h>

#define BATCH 4
#define CH 128
#define NPTS 4096
#define KNB 32
#define HID 512
#define BN_EPS 1e-5f

// ---------------- scratch (device globals; no allocations allowed) ----------------
__device__ float g_xT[BATCH * NPTS * CH];          // (B,N,C)
__device__ float g_qT[BATCH * NPTS * CH];
__device__ float g_kT[BATCH * NPTS * CH];
__device__ float g_vT[BATCH * NPTS * CH];
__device__ float g_sq[BATCH * NPTS];
__device__ float g_dist[67108864];                 // (B,N,N) 256MB
__device__ int   g_idx[BATCH * NPTS * KNB];
__device__ float g_y1[BATCH * CH * NPTS];          // attn + residual (pre-BN1)
__device__ float g_y2[BATCH * CH * NPTS];          // BN1 output
__device__ float g_h[BATCH * HID * NPTS];          // FFN hidden
__device__ float g_y3[BATCH * CH * NPTS];          // FFN + residual (pre-BN2)
__device__ float g_mean[CH];
__device__ float g_rstd[CH];

// ---------------- transpose x (B,C,N) -> xT (B,N,C) ----------------
__global__ void transpose_kernel(const float* __restrict__ x, float* __restrict__ xT) {
    __shared__ float tile[32][33];
    int b  = blockIdx.z;
    int n0 = blockIdx.x * 32;
    int c0 = blockIdx.y * 32;
    const float* xb = x + (size_t)b * CH * NPTS;
    float* xtb = xT + (size_t)b * NPTS * CH;
    int tx = threadIdx.x, ty = threadIdx.y;
    #pragma unroll
    for (int i = 0; i < 32; i += 8)
        tile[ty + i][tx] = xb[(size_t)(c0 + ty + i) * NPTS + n0 + tx];
    __syncthreads();
    #pragma unroll
    for (int i = 0; i < 32; i += 8)
        xtb[(size_t)(n0 + ty + i) * CH + c0 + tx] = tile[tx][ty + i];
}

// ---------------- squared norms sq[b][n] ----------------
__global__ void sq_kernel(const float* __restrict__ x, float* __restrict__ sq) {
    int b = blockIdx.y;
    int n = blockIdx.x * 256 + threadIdx.x;
    const float* xb = x + (size_t)b * CH * NPTS;
    float s = 0.f;
    #pragma unroll 8
    for (int c = 0; c < CH; c++) {
        float v = xb[(size_t)c * NPTS + n];
        s += v * v;
    }
    sq[b * NPTS + n] = s;
}

// ---------------- tiled SGEMM: C = A(MxK rm) * B(NxK rm)^T ----------------
// dist_epi: out = sqv[n] - 2*acc (for KNN distance ranking)
#define BM 64
#define BN 64
#define BKK 16

__global__ void gemm_nt_kernel(const float* __restrict__ Ag, const float* __restrict__ Bg,
                               float* __restrict__ Cg, const float* __restrict__ sqv,
                               int M, int Nn, int K, int dist_epi,
                               long sA, long sB, long sC, long sSq) {
    __shared__ float As[BKK][BM + 4];
    __shared__ float Bs[BKK][BN + 4];
    int b = blockIdx.z;
    const float* A = Ag + (long)b * sA;
    const float* B = Bg + (long)b * sB;
    float* Cmat = Cg + (long)b * sC;
    const float* sqb = sqv ? (sqv + (long)b * sSq) : nullptr;
    int m0 = blockIdx.y * BM, n0 = blockIdx.x * BN;
    int tid = threadIdx.x;
    int tx = tid & 15, ty = tid >> 4;
    float acc[4][4] = {};
    for (int k0 = 0; k0 < K; k0 += BKK) {
        #pragma unroll
        for (int r = 0; r < 4; r++) {
            int e = r * 256 + tid;
            int mm = e >> 4, kk = e & 15;
            As[kk][mm] = A[(long)(m0 + mm) * K + k0 + kk];
        }
        #pragma unroll
        for (int r = 0; r < 4; r++) {
            int e = r * 256 + tid;
            int nn = e >> 4, kk = e & 15;
            Bs[kk][nn] = B[(long)(n0 + nn) * K + k0 + kk];
        }
        __syncthreads();
        #pragma unroll
        for (int kk = 0; kk < BKK; kk++) {
            float ra[4], rb[4];
            #pragma unroll
            for (int i = 0; i < 4; i++) ra[i] = As[kk][ty * 4 + i];
            #pragma unroll
            for (int j = 0; j < 4; j++) rb[j] = Bs[kk][tx * 4 + j];
            #pragma unroll
            for (int i = 0; i < 4; i++)
                #pragma unroll
                for (int j = 0; j < 4; j++)
                    acc[i][j] += ra[i] * rb[j];
        }
        __syncthreads();
    }
    #pragma unroll
    for (int i = 0; i < 4; i++) {
        int mm = m0 + ty * 4 + i;
        int nn = n0 + tx * 4;
        float4 v;
        if (dist_epi) {
            v.x = sqb[nn + 0] - 2.f * acc[i][0];
            v.y = sqb[nn + 1] - 2.f * acc[i][1];
            v.z = sqb[nn + 2] - 2.f * acc[i][2];
            v.w = sqb[nn + 3] - 2.f * acc[i][3];
        } else {
            v.x = acc[i][0]; v.y = acc[i][1]; v.z = acc[i][2]; v.w = acc[i][3];
        }
        *reinterpret_cast<float4*>(&Cmat[(long)mm * Nn + nn]) = v;
    }
}

// ---------------- tiled SGEMM: C = A(MxK rm) * B(KxN rm) ----------------
// epi: 0 plain, 1 LeakyReLU(0.2), 2 add residual R
__global__ void gemm_nn_kernel(const float* __restrict__ Ag, const float* __restrict__ Bg,
                               float* __restrict__ Cg, const float* __restrict__ Rg,
                               int M, int Nn, int K, int epi,
                               long sA, long sB, long sC, long sR) {
    __shared__ float As[BKK][BM + 4];
    __shared__ float Bs[BKK][BN + 4];
    int b = blockIdx.z;
    const float* A = Ag + (long)b * sA;
    const float* B = Bg + (long)b * sB;
    float* Cmat = Cg + (long)b * sC;
    const float* R = Rg ? (Rg + (long)b * sR) : nullptr;
    int m0 = blockIdx.y * BM, n0 = blockIdx.x * BN;
    int tid = threadIdx.x;
    int tx = tid & 15, ty = tid >> 4;
    float acc[4][4] = {};
    for (int k0 = 0; k0 < K; k0 += BKK) {
        #pragma unroll
        for (int r = 0; r < 4; r++) {
            int e = r * 256 + tid;
            int mm = e >> 4, kk = e & 15;
            As[kk][mm] = A[(long)(m0 + mm) * K + k0 + kk];
        }
        #pragma unroll
        for (int r = 0; r < 4; r++) {
            int e = r * 256 + tid;
            int nn = e & 63, kk = e >> 6;
            Bs[kk][nn] = B[(long)(k0 + kk) * Nn + n0 + nn];
        }
        __syncthreads();
        #pragma unroll
        for (int kk = 0; kk < BKK; kk++) {
            float ra[4], rb[4];
            #pragma unroll
            for (int i = 0; i < 4; i++) ra[i] = As[kk][ty * 4 + i];
            #pragma unroll
            for (int j = 0; j < 4; j++) rb[j] = Bs[kk][tx * 4 + j];
            #pragma unroll
            for (int i = 0; i < 4; i++)
                #pragma unroll
                for (int j = 0; j < 4; j++)
                    acc[i][j] += ra[i] * rb[j];
        }
        __syncthreads();
    }
    #pragma unroll
    for (int i = 0; i < 4; i++) {
        int mm = m0 + ty * 4 + i;
        int nn = n0 + tx * 4;
        float4 v = {acc[i][0], acc[i][1], acc[i][2], acc[i][3]};
        if (epi == 1) {
            v.x = v.x >= 0.f ? v.x : 0.2f * v.x;
            v.y = v.y >= 0.f ? v.y : 0.2f * v.y;
            v.z = v.z >= 0.f ? v.z : 0.2f * v.z;
            v.w = v.w >= 0.f ? v.w : 0.2f * v.w;
        } else if (epi == 2) {
            float4 r4 = *reinterpret_cast<const float4*>(&R[(long)mm * Nn + nn]);
            v.x += r4.x; v.y += r4.y; v.z += r4.z; v.w += r4.w;
        }
        *reinterpret_cast<float4*>(&Cmat[(long)mm * Nn + nn]) = v;
    }
}

// ---------------- top-32 smallest per row (warp per row, iterative min-extract) ----------------
__global__ void topk_kernel(const float* __restrict__ dist, int* __restrict__ idx) {
    int warp = (blockIdx.x * blockDim.x + threadIdx.x) >> 5;
    int lane = threadIdx.x & 31;
    if (warp >= BATCH * NPTS) return;
    const float* row = dist + (size_t)warp * NPTS;
    float vmin = 3.4e38f;
    int limin = 0;
    #pragma unroll 4
    for (int i = 0; i < 128; i++) {
        float v = row[i * 32 + lane];
        if (v < vmin) { vmin = v; limin = i; }
    }
    int* out = idx + (size_t)warp * KNB;
    for (int r = 0; r < KNB; r++) {
        float bv = vmin;
        int bl = lane;
        #pragma unroll
        for (int off = 16; off; off >>= 1) {
            float ov = __shfl_xor_sync(0xffffffffu, bv, off);
            int   ol = __shfl_xor_sync(0xffffffffu, bl, off);
            if (ov < bv || (ov == bv && ol < bl)) { bv = ov; bl = ol; }
        }
        int wli = __shfl_sync(0xffffffffu, limin, bl);
        if (lane == r) out[r] = wli * 32 + bl;
        if (lane == bl) {
            // lane's extraction sequence is strictly increasing in (value, local-idx)
            // order, so "already consumed" == (v,i) <= (exv,exli). No mask needed.
            float exv = vmin;
            int exli = limin;
            vmin = 3.4e38f;
            limin = 0;
            for (int i = 0; i < 128; i++) {
                float v = row[i * 32 + lane];
                if (v > exv || (v == exv && i > exli)) {
                    if (v < vmin) { vmin = v; limin = i; }
                }
            }
        }
    }
}

// ---------------- fused gather + per-dim softmax attention + residual ----------------
// energy=(q-k)/sqrt(D), softmax over D (lane dim), out = sum_k attn*v; y1 = x + out
__global__ void attn_kernel(const float* __restrict__ qT, const float* __restrict__ kT,
                            const float* __restrict__ vT, const float* __restrict__ xT,
                            const int* __restrict__ idx, float* __restrict__ y1) {
    __shared__ float sh[CH * 33];
    int b  = blockIdx.x >> 7;           // NPTS/32 = 128 blocks per batch
    int n0 = (blockIdx.x & 127) << 5;
    int wid = threadIdx.x >> 5, lane = threadIdx.x & 31;
    const float inv = 0.17677669529663689f;  // 1/sqrt(32)
    for (int p = wid; p < 32; p += 8) {
        int n = n0 + p;
        size_t base = ((size_t)b * NPTS + n) * CH;
        float qr[4], kc[4], vc[4], o[4] = {0.f, 0.f, 0.f, 0.f};
        #pragma unroll
        for (int t = 0; t < 4; t++) {
            qr[t] = qT[base + t * 32 + lane];
            kc[t] = kT[base + t * 32 + lane];
            vc[t] = vT[base + t * 32 + lane];
        }
        int ji = idx[((size_t)b * NPTS + n) * KNB + lane];
        for (int r = 0; r < KNB; r++) {
            int j = __shfl_sync(0xffffffffu, ji, r);
            size_t jb = ((size_t)b * NPTS + j) * CH;
            #pragma unroll
            for (int t = 0; t < 4; t++) {
                float kn = kT[jb + t * 32 + lane] - kc[t];
                float vn = vT[jb + t * 32 + lane] - vc[t];
                float e = (qr[t] - kn) * inv;
                float m = e;
                #pragma unroll
                for (int off = 16; off; off >>= 1)
                    m = fmaxf(m, __shfl_xor_sync(0xffffffffu, m, off));
                float pe = __expf(e - m);
                float s = pe;
                #pragma unroll
                for (int off = 16; off; off >>= 1)
                    s += __shfl_xor_sync(0xffffffffu, s, off);
                o[t] += __fdividef(pe, s) * vn;
            }
        }
        #pragma unroll
        for (int t = 0; t < 4; t++) {
            float y = xT[base + t * 32 + lane] + o[t];
            sh[(t * 32 + lane) * 33 + p] = y;
        }
    }
    __syncthreads();
    size_t ob = (size_t)b * CH * NPTS;
    for (int e = threadIdx.x; e < CH * 32; e += 256) {
        int c = e >> 5, p = e & 31;
        y1[ob + (size_t)c * NPTS + n0 + p] = sh[c * 33 + p];
    }
}

// ---------------- BatchNorm stats per channel over (B, N) ----------------
__global__ void bn_stats_kernel(const float* __restrict__ y,
                                float* __restrict__ mean, float* __restrict__ rstd) {
    int c = blockIdx.x;
    __shared__ float ssum[256], ssq[256];
    float s = 0.f, s2 = 0.f;
    for (int b = 0; b < BATCH; b++) {
        const float* p = y + ((size_t)b * CH + c) * NPTS;
        for (int n = threadIdx.x; n < NPTS; n += 256) {
            float v = p[n];
            s += v;
            s2 += v * v;
        }
    }
    ssum[threadIdx.x] = s;
    ssq[threadIdx.x] = s2;
    __syncthreads();
    for (int st = 128; st; st >>= 1) {
        if (threadIdx.x < st) {
            ssum[threadIdx.x] += ssum[threadIdx.x + st];
            ssq[threadIdx.x] += ssq[threadIdx.x + st];
        }
        __syncthreads();
    }
    if (threadIdx.x == 0) {
        float inv_n = 1.f / (BATCH * NPTS);
        float m = ssum[0] * inv_n;
        float var = ssq[0] * inv_n - m * m;
        mean[c] = m;
        rstd[c] = rsqrtf(var + BN_EPS);
    }
}

__global__ void bn_apply_kernel(const float* __restrict__ y,
                                const float* __restrict__ mean, const float* __restrict__ rstd,
                                const float* __restrict__ g, const float* __restrict__ bta,
                                float* __restrict__ outp) {
    size_t i = (size_t)blockIdx.x * 256 + threadIdx.x;
    int c = (int)((i / NPTS) % CH);
    outp[i] = g[c] * (y[i] - mean[c]) * rstd[c] + bta[c];
}

// ---------------- host launch ----------------
extern "C" void kernel_launch(void* const* d_in, const int* in_sizes, int n_in,
                              void* d_out, int out_size) {
    const float* x  = (const float*)d_in[0];
    const float* Wq = (const float*)d_in[1];
    const float* Wk = (const float*)d_in[2];
    const float* Wv = (const float*)d_in[3];
    const float* W1 = (const float*)d_in[4];
    const float* W2 = (const float*)d_in[5];
    const float* g1 = (const float*)d_in[6];
    const float* b1 = (const float*)d_in[7];
    const float* g2 = (const float*)d_in[8];
    const float* b2 = (const float*)d_in[9];
    float* out = (float*)d_out;

    void *p;
    cudaGetSymbolAddress(&p, g_xT);   float* xT   = (float*)p;
    cudaGetSymbolAddress(&p, g_qT);   float* qT   = (float*)p;
    cudaGetSymbolAddress(&p, g_kT);   float* kT   = (float*)p;
    cudaGetSymbolAddress(&p, g_vT);   float* vT   = (float*)p;
    cudaGetSymbolAddress(&p, g_sq);   float* sq   = (float*)p;
    cudaGetSymbolAddress(&p, g_dist); float* dist = (float*)p;
    cudaGetSymbolAddress(&p, g_idx);  int*   idx  = (int*)p;
    cudaGetSymbolAddress(&p, g_y1);   float* y1   = (float*)p;
    cudaGetSymbolAddress(&p, g_y2);   float* y2   = (float*)p;
    cudaGetSymbolAddress(&p, g_h);    float* h    = (float*)p;
    cudaGetSymbolAddress(&p, g_y3);   float* y3   = (float*)p;
    cudaGetSymbolAddress(&p, g_mean); float* mean = (float*)p;
    cudaGetSymbolAddress(&p, g_rstd); float* rstd = (float*)p;

    const long NC = (long)NPTS * CH;
    const long CN = (long)CH * NPTS;
    const long HN = (long)HID * NPTS;
    const long NN = (long)NPTS * NPTS;

    transpose_kernel<<<dim3(NPTS / 32, CH / 32, BATCH), dim3(32, 8)>>>(x, xT);
    sq_kernel<<<dim3(NPTS / 256, BATCH), 256>>>(x, sq);

    // q/k/v projections: proj[b][n][o] = sum_c xT[b][n][c] * W[o][c]
    gemm_nt_kernel<<<dim3(CH / BN, NPTS / BM, BATCH), 256>>>(xT, Wq, qT, nullptr,
        NPTS, CH, CH, 0, NC, 0, NC, 0);
    gemm_nt_kernel<<<dim3(CH / BN, NPTS / BM, BATCH), 256>>>(xT, Wk, kT, nullptr,
        NPTS, CH, CH, 0, NC, 0, NC, 0);
    gemm_nt_kernel<<<dim3(CH / BN, NPTS / BM, BATCH), 256>>>(xT, Wv, vT, nullptr,
        NPTS, CH, CH, 0, NC, 0, NC, 0);

    // distance (ranking-equivalent): dist[i][j] = sq[j] - 2 <x_i, x_j>
    gemm_nt_kernel<<<dim3(NPTS / BN, NPTS / BM, BATCH), 256>>>(xT, xT, dist, sq,
        NPTS, NPTS, CH, 1, NC, NC, NN, NPTS);

    topk_kernel<<<(BATCH * NPTS) / 8, 256>>>(dist, idx);

    attn_kernel<<<BATCH * NPTS / 32, 256>>>(qT, kT, vT, xT, idx, y1);

    bn_stats_kernel<<<CH, 256>>>(y1, mean, rstd);
    bn_apply_kernel<<<(BATCH * CH * NPTS) / 256, 256>>>(y1, mean, rstd, g1, b1, y2);

    // FFN: h = leaky(W1 @ y2) ; y3 = y2 + W2 @ h
    gemm_nn_kernel<<<dim3(NPTS / BN, HID / BM, BATCH), 256>>>(W1, y2, h, nullptr,
        HID, NPTS, CH, 1, 0, CN, HN, 0);
    gemm_nn_kernel<<<dim3(NPTS / BN, CH / BM, BATCH), 256>>>(W2, h, y3, y2,
        CH, NPTS, HID, 2, 0, HN, CN, CN);

    bn_stats_kernel<<<CH, 256>>>(y3, mean, rstd);
    bn_apply_kernel<<<(BATCH * CH * NPTS) / 256, 256>>>(y3, mean, rstd, g2, b2, out);
}

// round 2
// speedup vs baseline: 1.0587x; 1.0587x over previous
#include <cuda_runtime.h>
#include <math.h>

#define BATCH 4
#define CH 128
#define NPTS 4096
#define KNB 32
#define HID 512
#define BN_EPS 1e-5f

// ---------------- scratch (device globals; no allocations allowed) ----------------
__device__ float g_xT[BATCH * NPTS * CH];          // (B,N,C)
__device__ float g_xhi[BATCH * NPTS * CH];
__device__ float g_xlo[BATCH * NPTS * CH];
__device__ float g_qT[BATCH * NPTS * CH];
__device__ float g_kT[BATCH * NPTS * CH];
__device__ float g_vT[BATCH * NPTS * CH];
__device__ float g_sq[BATCH * NPTS];
__device__ float g_dist[67108864];                 // (B,N,N) 256MB
__device__ int   g_idx[BATCH * NPTS * KNB];
__device__ float g_y1T[BATCH * NPTS * CH];         // attn + residual (pre-BN1), (B,N,C)
__device__ float g_y2T[BATCH * NPTS * CH];         // BN1 output
__device__ float g_y2hi[BATCH * NPTS * CH];
__device__ float g_y2lo[BATCH * NPTS * CH];
__device__ float g_hhi[BATCH * NPTS * HID];        // FFN hidden (hi/lo only)
__device__ float g_hlo[BATCH * NPTS * HID];
__device__ float g_y3T[BATCH * NPTS * CH];         // FFN + residual (pre-BN2)
__device__ float g_wqhi[CH * CH];
__device__ float g_wqlo[CH * CH];
__device__ float g_wkhi[CH * CH];
__device__ float g_wklo[CH * CH];
__device__ float g_wvhi[CH * CH];
__device__ float g_wvlo[CH * CH];
__device__ float g_w1hi[HID * CH];
__device__ float g_w1lo[HID * CH];
__device__ float g_w2hi[CH * HID];
__device__ float g_w2lo[CH * HID];
__device__ float g_psum[64 * CH];
__device__ float g_psq[64 * CH];
__device__ float g_mean[CH];
__device__ float g_rstd[CH];

__device__ __forceinline__ float to_tf32(float x) {
    unsigned u;
    asm("cvt.rna.tf32.f32 %0, %1;" : "=r"(u) : "f"(x));
    return __uint_as_float(u);
}

__device__ __forceinline__ void mma_tf32(float c[4], const float a[4], const float b[2]) {
    asm volatile(
        "mma.sync.aligned.m16n8k8.row.col.f32.tf32.tf32.f32 "
        "{%0,%1,%2,%3}, {%4,%5,%6,%7}, {%8,%9}, {%0,%1,%2,%3};\n"
        : "+f"(c[0]), "+f"(c[1]), "+f"(c[2]), "+f"(c[3])
        : "r"(__float_as_uint(a[0])), "r"(__float_as_uint(a[1])),
          "r"(__float_as_uint(a[2])), "r"(__float_as_uint(a[3])),
          "r"(__float_as_uint(b[0])), "r"(__float_as_uint(b[1])));
}

// ---------------- transpose x (B,C,N) -> xT (B,N,C) + tf32 hi/lo ----------------
__global__ void transpose_kernel(const float* __restrict__ x, float* __restrict__ xT,
                                 float* __restrict__ xhi, float* __restrict__ xlo) {
    __shared__ float tile[32][33];
    int b  = blockIdx.z;
    int n0 = blockIdx.x * 32;
    int c0 = blockIdx.y * 32;
    const float* xb = x + (size_t)b * CH * NPTS;
    size_t ob = (size_t)b * NPTS * CH;
    int tx = threadIdx.x, ty = threadIdx.y;
    #pragma unroll
    for (int i = 0; i < 32; i += 8)
        tile[ty + i][tx] = xb[(size_t)(c0 + ty + i) * NPTS + n0 + tx];
    __syncthreads();
    #pragma unroll
    for (int i = 0; i < 32; i += 8) {
        float v = tile[tx][ty + i];
        size_t o = ob + (size_t)(n0 + ty + i) * CH + c0 + tx;
        float h = to_tf32(v);
        xT[o] = v;
        xhi[o] = h;
        xlo[o] = to_tf32(v - h);
    }
}

// ---------------- elementwise tf32 hi/lo split ----------------
__global__ void hilo_kernel(const float* __restrict__ src, float* __restrict__ hi,
                            float* __restrict__ lo, int n) {
    int i = blockIdx.x * 256 + threadIdx.x;
    if (i < n) {
        float v = src[i];
        float h = to_tf32(v);
        hi[i] = h;
        lo[i] = to_tf32(v - h);
    }
}

// ---------------- squared norms sq[b][n] ----------------
__global__ void sq_kernel(const float* __restrict__ x, float* __restrict__ sq) {
    int b = blockIdx.y;
    int n = blockIdx.x * 256 + threadIdx.x;
    const float* xb = x + (size_t)b * CH * NPTS;
    float s = 0.f;
    #pragma unroll 8
    for (int c = 0; c < CH; c++) {
        float v = xb[(size_t)c * NPTS + n];
        s += v * v;
    }
    sq[b * NPTS + n] = s;
}

// ---------------- 3xTF32 tensor-core NT GEMM: C = A(MxK) * B(NnxK)^T ----------------
// epi 0: C = acc
// epi 1: C = Aux[n] - 2*acc                (distance)
// epi 2: leaky(acc) -> write hi (Cg) and lo (C2) only
// epi 3: C = acc + Aux[m*Nn+n]             (residual)
__global__ __launch_bounds__(256) void mma_nt_kernel(
    const float* __restrict__ Ahi, const float* __restrict__ Alo,
    const float* __restrict__ Bhi, const float* __restrict__ Blo,
    float* __restrict__ Cg, float* __restrict__ C2,
    const float* __restrict__ Aux,
    int M, int Nn, int K, int epi,
    long sA, long sB, long sC, long sAux) {
    __shared__ float As[2][128][20];
    __shared__ float Bs[2][128][20];
    int b = blockIdx.z;
    const float* Ah = Ahi + (long)b * sA;
    const float* Al = Alo + (long)b * sA;
    const float* Bh = Bhi + (long)b * sB;
    const float* Bl = Blo + (long)b * sB;
    int m0 = blockIdx.y * 128, n0 = blockIdx.x * 128;
    int tid = threadIdx.x, lane = tid & 31, warp = tid >> 5;
    int wm = (warp & 1) * 64;
    int wn = (warp >> 1) * 32;
    int qrow = lane >> 2, qcol = lane & 3;
    float acc[4][4][4] = {};

    int lrow = tid >> 2, lc4 = (tid & 3) * 4;       // load mapping: idx = i*256+tid
    for (int k0 = 0; k0 < K; k0 += 16) {
        #pragma unroll
        for (int i = 0; i < 2; i++) {
            int row = i * 64 + lrow;
            const float4* pAh = reinterpret_cast<const float4*>(&Ah[(long)(m0 + row) * K + k0 + lc4]);
            const float4* pAl = reinterpret_cast<const float4*>(&Al[(long)(m0 + row) * K + k0 + lc4]);
            const float4* pBh = reinterpret_cast<const float4*>(&Bh[(long)(n0 + row) * K + k0 + lc4]);
            const float4* pBl = reinterpret_cast<const float4*>(&Bl[(long)(n0 + row) * K + k0 + lc4]);
            *reinterpret_cast<float4*>(&As[0][row][lc4]) = *pAh;
            *reinterpret_cast<float4*>(&As[1][row][lc4]) = *pAl;
            *reinterpret_cast<float4*>(&Bs[0][row][lc4]) = *pBh;
            *reinterpret_cast<float4*>(&Bs[1][row][lc4]) = *pBl;
        }
        __syncthreads();
        #pragma unroll
        for (int ks = 0; ks < 2; ks++) {
            int kc = ks * 8;
            float ah[4][4], al[4][4], bh[4][2], bl[4][2];
            #pragma unroll
            for (int f = 0; f < 4; f++) {
                int r0 = wm + f * 16 + qrow;
                ah[f][0] = As[0][r0][kc + qcol];
                ah[f][1] = As[0][r0 + 8][kc + qcol];
                ah[f][2] = As[0][r0][kc + qcol + 4];
                ah[f][3] = As[0][r0 + 8][kc + qcol + 4];
                al[f][0] = As[1][r0][kc + qcol];
                al[f][1] = As[1][r0 + 8][kc + qcol];
                al[f][2] = As[1][r0][kc + qcol + 4];
                al[f][3] = As[1][r0 + 8][kc + qcol + 4];
            }
            #pragma unroll
            for (int g = 0; g < 4; g++) {
                int c0 = wn + g * 8 + qrow;
                bh[g][0] = Bs[0][c0][kc + qcol];
                bh[g][1] = Bs[0][c0][kc + qcol + 4];
                bl[g][0] = Bs[1][c0][kc + qcol];
                bl[g][1] = Bs[1][c0][kc + qcol + 4];
            }
            #pragma unroll
            for (int f = 0; f < 4; f++)
                #pragma unroll
                for (int g = 0; g < 4; g++) {
                    mma_tf32(acc[f][g], ah[f], bh[g]);
                    mma_tf32(acc[f][g], ah[f], bl[g]);
                    mma_tf32(acc[f][g], al[f], bh[g]);
                }
        }
        __syncthreads();
    }

    float* Cb = Cg + (long)b * sC;
    #pragma unroll
    for (int f = 0; f < 4; f++) {
        int r0 = m0 + wm + f * 16 + qrow;
        #pragma unroll
        for (int g = 0; g < 4; g++) {
            int cc = n0 + wn + g * 8 + qcol * 2;
            float v0 = acc[f][g][0], v1 = acc[f][g][1];
            float v2 = acc[f][g][2], v3 = acc[f][g][3];
            if (epi == 1) {
                const float* sqb = Aux + (long)b * sAux;
                v0 = sqb[cc] - 2.f * v0;
                v1 = sqb[cc + 1] - 2.f * v1;
                v2 = sqb[cc] - 2.f * v2;
                v3 = sqb[cc + 1] - 2.f * v3;
            } else if (epi == 3) {
                const float* R = Aux + (long)b * sAux;
                v0 += R[(long)r0 * Nn + cc];
                v1 += R[(long)r0 * Nn + cc + 1];
                v2 += R[(long)(r0 + 8) * Nn + cc];
                v3 += R[(long)(r0 + 8) * Nn + cc + 1];
            }
            if (epi == 2) {
                float* Hb = Cg + (long)b * sC;
                float* Lb = C2 + (long)b * sC;
                v0 = v0 >= 0.f ? v0 : 0.2f * v0;
                v1 = v1 >= 0.f ? v1 : 0.2f * v1;
                v2 = v2 >= 0.f ? v2 : 0.2f * v2;
                v3 = v3 >= 0.f ? v3 : 0.2f * v3;
                float h0 = to_tf32(v0), h1 = to_tf32(v1);
                float h2 = to_tf32(v2), h3 = to_tf32(v3);
                *reinterpret_cast<float2*>(&Hb[(long)r0 * Nn + cc]) = make_float2(h0, h1);
                *reinterpret_cast<float2*>(&Hb[(long)(r0 + 8) * Nn + cc]) = make_float2(h2, h3);
                *reinterpret_cast<float2*>(&Lb[(long)r0 * Nn + cc]) =
                    make_float2(to_tf32(v0 - h0), to_tf32(v1 - h1));
                *reinterpret_cast<float2*>(&Lb[(long)(r0 + 8) * Nn + cc]) =
                    make_float2(to_tf32(v2 - h2), to_tf32(v3 - h3));
            } else {
                *reinterpret_cast<float2*>(&Cb[(long)r0 * Nn + cc]) = make_float2(v0, v1);
                *reinterpret_cast<float2*>(&Cb[(long)(r0 + 8) * Nn + cc]) = make_float2(v2, v3);
            }
        }
    }
}

// ---------------- top-32 smallest per row (warp per row, iterative min-extract) ----------------
__global__ void topk_kernel(const float* __restrict__ dist, int* __restrict__ idx) {
    int warp = (blockIdx.x * blockDim.x + threadIdx.x) >> 5;
    int lane = threadIdx.x & 31;
    if (warp >= BATCH * NPTS) return;
    const float* row = dist + (size_t)warp * NPTS;
    float vmin = 3.4e38f;
    int limin = 0;
    #pragma unroll 4
    for (int i = 0; i < 128; i++) {
        float v = row[i * 32 + lane];
        if (v < vmin) { vmin = v; limin = i; }
    }
    int* out = idx + (size_t)warp * KNB;
    for (int r = 0; r < KNB; r++) {
        float bv = vmin;
        int bl = lane;
        #pragma unroll
        for (int off = 16; off; off >>= 1) {
            float ov = __shfl_xor_sync(0xffffffffu, bv, off);
            int   ol = __shfl_xor_sync(0xffffffffu, bl, off);
            if (ov < bv || (ov == bv && ol < bl)) { bv = ov; bl = ol; }
        }
        int wli = __shfl_sync(0xffffffffu, limin, bl);
        if (lane == r) out[r] = wli * 32 + bl;
        if (lane == bl) {
            float exv = vmin;
            int exli = limin;
            vmin = 3.4e38f;
            limin = 0;
            for (int i = 0; i < 128; i++) {
                float v = row[i * 32 + lane];
                if (v > exv || (v == exv && i > exli)) {
                    if (v < vmin) { vmin = v; limin = i; }
                }
            }
        }
    }
}

// ---------------- fused gather + per-dim softmax attention + residual -> y1T (B,N,C) ----------------
__global__ void attn_kernel(const float* __restrict__ qT, const float* __restrict__ kT,
                            const float* __restrict__ vT, const float* __restrict__ xT,
                            const int* __restrict__ idx, float* __restrict__ y1T) {
    int b  = blockIdx.x >> 7;
    int n0 = (blockIdx.x & 127) << 5;
    int wid = threadIdx.x >> 5, lane = threadIdx.x & 31;
    const float inv = 0.17677669529663689f;  // 1/sqrt(32)
    for (int p = wid; p < 32; p += 8) {
        int n = n0 + p;
        size_t base = ((size_t)b * NPTS + n) * CH;
        float qr[4], kc[4], vc[4], o[4] = {0.f, 0.f, 0.f, 0.f};
        #pragma unroll
        for (int t = 0; t < 4; t++) {
            qr[t] = qT[base + t * 32 + lane];
            kc[t] = kT[base + t * 32 + lane];
            vc[t] = vT[base + t * 32 + lane];
        }
        int ji = idx[((size_t)b * NPTS + n) * KNB + lane];
        for (int r = 0; r < KNB; r++) {
            int j = __shfl_sync(0xffffffffu, ji, r);
            size_t jb = ((size_t)b * NPTS + j) * CH;
            #pragma unroll
            for (int t = 0; t < 4; t++) {
                float kn = kT[jb + t * 32 + lane] - kc[t];
                float vn = vT[jb + t * 32 + lane] - vc[t];
                float e = (qr[t] - kn) * inv;
                float m = e;
                #pragma unroll
                for (int off = 16; off; off >>= 1)
                    m = fmaxf(m, __shfl_xor_sync(0xffffffffu, m, off));
                float pe = __expf(e - m);
                float s = pe;
                #pragma unroll
                for (int off = 16; off; off >>= 1)
                    s += __shfl_xor_sync(0xffffffffu, s, off);
                o[t] += __fdividef(pe, s) * vn;
            }
        }
        #pragma unroll
        for (int t = 0; t < 4; t++)
            y1T[base + t * 32 + lane] = xT[base + t * 32 + lane] + o[t];
    }
}

// ---------------- BatchNorm stats on (B,N,C): stage 1 partials ----------------
__global__ void bn_part_kernel(const float* __restrict__ yT,
                               float* __restrict__ psum, float* __restrict__ psq) {
    __shared__ float s1[8][CH], s2[8][CH];
    int blk = blockIdx.x;            // 64 blocks x 256 rows
    int t = threadIdx.x;
    int c4 = (t & 31) * 4;
    int rg = t >> 5;
    float a0 = 0, a1 = 0, a2 = 0, a3 = 0, q0 = 0, q1 = 0, q2 = 0, q3 = 0;
    for (int rr = rg; rr < 256; rr += 8) {
        size_t row = (size_t)blk * 256 + rr;
        float4 v = *reinterpret_cast<const float4*>(yT + row * CH + c4);
        a0 += v.x; a1 += v.y; a2 += v.z; a3 += v.w;
        q0 += v.x * v.x; q1 += v.y * v.y; q2 += v.z * v.z; q3 += v.w * v.w;
    }
    s1[rg][c4] = a0; s1[rg][c4 + 1] = a1; s1[rg][c4 + 2] = a2; s1[rg][c4 + 3] = a3;
    s2[rg][c4] = q0; s2[rg][c4 + 1] = q1; s2[rg][c4 + 2] = q2; s2[rg][c4 + 3] = q3;
    __syncthreads();
    if (t < CH) {
        float s = 0, q = 0;
        #pragma unroll
        for (int r = 0; r < 8; r++) { s += s1[r][t]; q += s2[r][t]; }
        psum[blk * CH + t] = s;
        psq[blk * CH + t] = q;
    }
}

__global__ void bn_final_kernel(const float* __restrict__ psum, const float* __restrict__ psq,
                                float* __restrict__ mean, float* __restrict__ rstd) {
    int c = threadIdx.x;
    float s = 0, q = 0;
    for (int b = 0; b < 64; b++) { s += psum[b * CH + c]; q += psq[b * CH + c]; }
    float inv_n = 1.f / (BATCH * NPTS);
    float m = s * inv_n;
    float v = q * inv_n - m * m;
    mean[c] = m;
    rstd[c] = rsqrtf(v + BN_EPS);
}

// ---------------- BN apply on (B,N,C), optional tf32 hi/lo emit ----------------
__global__ void bn_apply_kernel(const float* __restrict__ yT,
                                const float* __restrict__ mean, const float* __restrict__ rstd,
                                const float* __restrict__ g, const float* __restrict__ bta,
                                float* __restrict__ out, float* __restrict__ ohi,
                                float* __restrict__ olo) {
    size_t i = (size_t)blockIdx.x * 256 + threadIdx.x;
    int c = (int)(i & (CH - 1));
    float y = g[c] * (yT[i] - mean[c]) * rstd[c] + bta[c];
    out[i] = y;
    if (ohi) {
        float h = to_tf32(y);
        ohi[i] = h;
        olo[i] = to_tf32(y - h);
    }
}

// ---------------- final BN apply + transpose (B,N,C) -> (B,C,N) ----------------
__global__ void bn_apply_t_kernel(const float* __restrict__ yT,
                                  const float* __restrict__ mean, const float* __restrict__ rstd,
                                  const float* __restrict__ g, const float* __restrict__ bta,
                                  float* __restrict__ out) {
    __shared__ float tile[32][33];
    int b  = blockIdx.z;
    int n0 = blockIdx.x * 32;
    int c0 = blockIdx.y * 32;
    int tx = threadIdx.x, ty = threadIdx.y;
    const float* y = yT + (size_t)b * NPTS * CH;
    #pragma unroll
    for (int i = 0; i < 32; i += 8) {
        int c = c0 + tx;
        float v = y[(size_t)(n0 + ty + i) * CH + c];
        tile[ty + i][tx] = g[c] * (v - mean[c]) * rstd[c] + bta[c];
    }
    __syncthreads();
    float* ob = out + (size_t)b * CH * NPTS;
    #pragma unroll
    for (int i = 0; i < 32; i += 8)
        ob[(size_t)(c0 + ty + i) * NPTS + n0 + tx] = tile[tx][ty + i];
}

// ---------------- host launch ----------------
extern "C" void kernel_launch(void* const* d_in, const int* in_sizes, int n_in,
                              void* d_out, int out_size) {
    const float* x  = (const float*)d_in[0];
    const float* Wq = (const float*)d_in[1];
    const float* Wk = (const float*)d_in[2];
    const float* Wv = (const float*)d_in[3];
    const float* W1 = (const float*)d_in[4];
    const float* W2 = (const float*)d_in[5];
    const float* g1 = (const float*)d_in[6];
    const float* b1 = (const float*)d_in[7];
    const float* g2 = (const float*)d_in[8];
    const float* b2 = (const float*)d_in[9];
    float* out = (float*)d_out;

    void* p;
    cudaGetSymbolAddress(&p, g_xT);   float* xT   = (float*)p;
    cudaGetSymbolAddress(&p, g_xhi);  float* xhi  = (float*)p;
    cudaGetSymbolAddress(&p, g_xlo);  float* xlo  = (float*)p;
    cudaGetSymbolAddress(&p, g_qT);   float* qT   = (float*)p;
    cudaGetSymbolAddress(&p, g_kT);   float* kT   = (float*)p;
    cudaGetSymbolAddress(&p, g_vT);   float* vT   = (float*)p;
    cudaGetSymbolAddress(&p, g_sq);   float* sq   = (float*)p;
    cudaGetSymbolAddress(&p, g_dist); float* dist = (float*)p;
    cudaGetSymbolAddress(&p, g_idx);  int*   idx  = (int*)p;
    cudaGetSymbolAddress(&p, g_y1T);  float* y1T  = (float*)p;
    cudaGetSymbolAddress(&p, g_y2T);  float* y2T  = (float*)p;
    cudaGetSymbolAddress(&p, g_y2hi); float* y2hi = (float*)p;
    cudaGetSymbolAddress(&p, g_y2lo); float* y2lo = (float*)p;
    cudaGetSymbolAddress(&p, g_hhi);  float* hhi  = (float*)p;
    cudaGetSymbolAddress(&p, g_hlo);  float* hlo  = (float*)p;
    cudaGetSymbolAddress(&p, g_y3T);  float* y3T  = (float*)p;
    cudaGetSymbolAddress(&p, g_wqhi); float* wqhi = (float*)p;
    cudaGetSymbolAddress(&p, g_wqlo); float* wqlo = (float*)p;
    cudaGetSymbolAddress(&p, g_wkhi); float* wkhi = (float*)p;
    cudaGetSymbolAddress(&p, g_wklo); float* wklo = (float*)p;
    cudaGetSymbolAddress(&p, g_wvhi); float* wvhi = (float*)p;
    cudaGetSymbolAddress(&p, g_wvlo); float* wvlo = (float*)p;
    cudaGetSymbolAddress(&p, g_w1hi); float* w1hi = (float*)p;
    cudaGetSymbolAddress(&p, g_w1lo); float* w1lo = (float*)p;
    cudaGetSymbolAddress(&p, g_w2hi); float* w2hi = (float*)p;
    cudaGetSymbolAddress(&p, g_w2lo); float* w2lo = (float*)p;
    cudaGetSymbolAddress(&p, g_psum); float* psum = (float*)p;
    cudaGetSymbolAddress(&p, g_psq);  float* psq  = (float*)p;
    cudaGetSymbolAddress(&p, g_mean); float* mean = (float*)p;
    cudaGetSymbolAddress(&p, g_rstd); float* rstd = (float*)p;

    const long NC = (long)NPTS * CH;
    const long NH = (long)NPTS * HID;
    const long NN = (long)NPTS * NPTS;

    transpose_kernel<<<dim3(NPTS / 32, CH / 32, BATCH), dim3(32, 8)>>>(x, xT, xhi, xlo);
    sq_kernel<<<dim3(NPTS / 256, BATCH), 256>>>(x, sq);

    hilo_kernel<<<(CH * CH + 255) / 256, 256>>>(Wq, wqhi, wqlo, CH * CH);
    hilo_kernel<<<(CH * CH + 255) / 256, 256>>>(Wk, wkhi, wklo, CH * CH);
    hilo_kernel<<<(CH * CH + 255) / 256, 256>>>(Wv, wvhi, wvlo, CH * CH);
    hilo_kernel<<<(HID * CH + 255) / 256, 256>>>(W1, w1hi, w1lo, HID * CH);
    hilo_kernel<<<(CH * HID + 255) / 256, 256>>>(W2, w2hi, w2lo, CH * HID);

    // projections: (NPTS x CH) = xT (NPTS x CH) * W^T
    mma_nt_kernel<<<dim3(1, NPTS / 128, BATCH), 256>>>(xhi, xlo, wqhi, wqlo, qT, nullptr,
        nullptr, NPTS, CH, CH, 0, NC, 0, NC, 0);
    mma_nt_kernel<<<dim3(1, NPTS / 128, BATCH), 256>>>(xhi, xlo, wkhi, wklo, kT, nullptr,
        nullptr, NPTS, CH, CH, 0, NC, 0, NC, 0);
    mma_nt_kernel<<<dim3(1, NPTS / 128, BATCH), 256>>>(xhi, xlo, wvhi, wvlo, vT, nullptr,
        nullptr, NPTS, CH, CH, 0, NC, 0, NC, 0);

    // distance (ranking-equivalent): dist[i][j] = sq[j] - 2 <x_i, x_j>
    mma_nt_kernel<<<dim3(NPTS / 128, NPTS / 128, BATCH), 256>>>(xhi, xlo, xhi, xlo, dist, nullptr,
        sq, NPTS, NPTS, CH, 1, NC, NC, NN, NPTS);

    topk_kernel<<<(BATCH * NPTS) / 8, 256>>>(dist, idx);

    attn_kernel<<<BATCH * NPTS / 32, 256>>>(qT, kT, vT, xT, idx, y1T);

    bn_part_kernel<<<64, 256>>>(y1T, psum, psq);
    bn_final_kernel<<<1, CH>>>(psum, psq, mean, rstd);
    bn_apply_kernel<<<(int)(BATCH * NC / 256), 256>>>(y1T, mean, rstd, g1, b1, y2T, y2hi, y2lo);

    // FFN: hT = leaky(y2T * W1^T) (hi/lo); y3T = hT * W2^T + y2T
    mma_nt_kernel<<<dim3(HID / 128, NPTS / 128, BATCH), 256>>>(y2hi, y2lo, w1hi, w1lo, hhi, hlo,
        nullptr, NPTS, HID, CH, 2, NC, 0, NH, 0);
    mma_nt_kernel<<<dim3(1, NPTS / 128, BATCH), 256>>>(hhi, hlo, w2hi, w2lo, y3T, nullptr,
        y2T, NPTS, CH, HID, 3, NH, 0, NC, NC);

    bn_part_kernel<<<64, 256>>>(y3T, psum, psq);
    bn_final_kernel<<<1, CH>>>(psum, psq, mean, rstd);
    bn_apply_t_kernel<<<dim3(NPTS / 32, CH / 32, BATCH), dim3(32, 8)>>>(y3T, mean, rstd, g2, b2, out);
}

// round 3
// speedup vs baseline: 1.3227x; 1.2494x over previous
#include <cuda_runtime.h>
#include <math.h>

#define BATCH 4
#define CH 128
#define NPTS 4096
#define KNB 32
#define HID 512
#define BN_EPS 1e-5f

// ---------------- scratch (device globals; no allocations allowed) ----------------
__device__ float g_xT[BATCH * NPTS * CH];          // (B,N,C)
__device__ float g_xhi[BATCH * NPTS * CH];
__device__ float g_xlo[BATCH * NPTS * CH];
__device__ float g_qT[BATCH * NPTS * CH];
__device__ float g_kT[BATCH * NPTS * CH];
__device__ float g_vT[BATCH * NPTS * CH];
__device__ float g_sq[BATCH * NPTS];
__device__ float g_dist[67108864];                 // (B,N,N) 268MB
__device__ int   g_idx[BATCH * NPTS * KNB];
__device__ float g_y1T[BATCH * NPTS * CH];         // attn + residual (pre-BN1), (B,N,C)
__device__ float g_y2T[BATCH * NPTS * CH];         // BN1 output
__device__ float g_y2hi[BATCH * NPTS * CH];
__device__ float g_y2lo[BATCH * NPTS * CH];
__device__ float g_hhi[BATCH * NPTS * HID];        // FFN hidden (hi/lo only)
__device__ float g_hlo[BATCH * NPTS * HID];
__device__ float g_y3T[BATCH * NPTS * CH];         // FFN + residual (pre-BN2)
__device__ float g_wqhi[CH * CH];
__device__ float g_wqlo[CH * CH];
__device__ float g_wkhi[CH * CH];
__device__ float g_wklo[CH * CH];
__device__ float g_wvhi[CH * CH];
__device__ float g_wvlo[CH * CH];
__device__ float g_w1hi[HID * CH];
__device__ float g_w1lo[HID * CH];
__device__ float g_w2hi[CH * HID];
__device__ float g_w2lo[CH * HID];
__device__ float g_psum[64 * CH];
__device__ float g_psq[64 * CH];
__device__ float g_mean[CH];
__device__ float g_rstd[CH];

__device__ __forceinline__ float to_tf32(float x) {
    unsigned u;
    asm("cvt.rna.tf32.f32 %0, %1;" : "=r"(u) : "f"(x));
    return __uint_as_float(u);
}

__device__ __forceinline__ void mma_tf32(float c[4], const float a[4], const float b[2]) {
    asm volatile(
        "mma.sync.aligned.m16n8k8.row.col.f32.tf32.tf32.f32 "
        "{%0,%1,%2,%3}, {%4,%5,%6,%7}, {%8,%9}, {%0,%1,%2,%3};\n"
        : "+f"(c[0]), "+f"(c[1]), "+f"(c[2]), "+f"(c[3])
        : "r"(__float_as_uint(a[0])), "r"(__float_as_uint(a[1])),
          "r"(__float_as_uint(a[2])), "r"(__float_as_uint(a[3])),
          "r"(__float_as_uint(b[0])), "r"(__float_as_uint(b[1])));
}

// ---------------- transpose x (B,C,N) -> xT (B,N,C) + tf32 hi/lo ----------------
__global__ void transpose_kernel(const float* __restrict__ x, float* __restrict__ xT,
                                 float* __restrict__ xhi, float* __restrict__ xlo) {
    __shared__ float tile[32][33];
    int b  = blockIdx.z;
    int n0 = blockIdx.x * 32;
    int c0 = blockIdx.y * 32;
    const float* xb = x + (size_t)b * CH * NPTS;
    size_t ob = (size_t)b * NPTS * CH;
    int tx = threadIdx.x, ty = threadIdx.y;
    #pragma unroll
    for (int i = 0; i < 32; i += 8)
        tile[ty + i][tx] = xb[(size_t)(c0 + ty + i) * NPTS + n0 + tx];
    __syncthreads();
    #pragma unroll
    for (int i = 0; i < 32; i += 8) {
        float v = tile[tx][ty + i];
        size_t o = ob + (size_t)(n0 + ty + i) * CH + c0 + tx;
        float h = to_tf32(v);
        xT[o] = v;
        xhi[o] = h;
        xlo[o] = to_tf32(v - h);
    }
}

// ---------------- elementwise tf32 hi/lo split ----------------
__global__ void hilo_kernel(const float* __restrict__ src, float* __restrict__ hi,
                            float* __restrict__ lo, int n) {
    int i = blockIdx.x * 256 + threadIdx.x;
    if (i < n) {
        float v = src[i];
        float h = to_tf32(v);
        hi[i] = h;
        lo[i] = to_tf32(v - h);
    }
}

// ---------------- squared norms sq[b][n] ----------------
__global__ void sq_kernel(const float* __restrict__ x, float* __restrict__ sq) {
    int b = blockIdx.y;
    int n = blockIdx.x * 256 + threadIdx.x;
    const float* xb = x + (size_t)b * CH * NPTS;
    float s = 0.f;
    #pragma unroll 8
    for (int c = 0; c < CH; c++) {
        float v = xb[(size_t)c * NPTS + n];
        s += v * v;
    }
    sq[b * NPTS + n] = s;
}

// ---------------- 3xTF32 tensor-core NT GEMM: C = A(MxK) * B(NnxK)^T ----------------
// epi 0: C = acc
// epi 1: C = Aux[n] - 2*acc                (distance)
// epi 2: leaky(acc) -> write hi (Cg) and lo (C2) only
// epi 3: C = acc + Aux[m*Nn+n]             (residual)
__global__ __launch_bounds__(256) void mma_nt_kernel(
    const float* __restrict__ Ahi, const float* __restrict__ Alo,
    const float* __restrict__ Bhi, const float* __restrict__ Blo,
    float* __restrict__ Cg, float* __restrict__ C2,
    const float* __restrict__ Aux,
    int M, int Nn, int K, int epi,
    long sA, long sB, long sC, long sAux) {
    __shared__ float As[2][128][20];
    __shared__ float Bs[2][128][20];
    int b = blockIdx.z;
    const float* Ah = Ahi + (long)b * sA;
    const float* Al = Alo + (long)b * sA;
    const float* Bh = Bhi + (long)b * sB;
    const float* Bl = Blo + (long)b * sB;
    int m0 = blockIdx.y * 128, n0 = blockIdx.x * 128;
    int tid = threadIdx.x, lane = tid & 31, warp = tid >> 5;
    int wm = (warp & 1) * 64;
    int wn = (warp >> 1) * 32;
    int qrow = lane >> 2, qcol = lane & 3;
    float acc[4][4][4] = {};

    int lrow = tid >> 2, lc4 = (tid & 3) * 4;       // load mapping: idx = i*256+tid
    for (int k0 = 0; k0 < K; k0 += 16) {
        #pragma unroll
        for (int i = 0; i < 2; i++) {
            int row = i * 64 + lrow;
            const float4* pAh = reinterpret_cast<const float4*>(&Ah[(long)(m0 + row) * K + k0 + lc4]);
            const float4* pAl = reinterpret_cast<const float4*>(&Al[(long)(m0 + row) * K + k0 + lc4]);
            const float4* pBh = reinterpret_cast<const float4*>(&Bh[(long)(n0 + row) * K + k0 + lc4]);
            const float4* pBl = reinterpret_cast<const float4*>(&Bl[(long)(n0 + row) * K + k0 + lc4]);
            *reinterpret_cast<float4*>(&As[0][row][lc4]) = *pAh;
            *reinterpret_cast<float4*>(&As[1][row][lc4]) = *pAl;
            *reinterpret_cast<float4*>(&Bs[0][row][lc4]) = *pBh;
            *reinterpret_cast<float4*>(&Bs[1][row][lc4]) = *pBl;
        }
        __syncthreads();
        #pragma unroll
        for (int ks = 0; ks < 2; ks++) {
            int kc = ks * 8;
            float ah[4][4], al[4][4], bh[4][2], bl[4][2];
            #pragma unroll
            for (int f = 0; f < 4; f++) {
                int r0 = wm + f * 16 + qrow;
                ah[f][0] = As[0][r0][kc + qcol];
                ah[f][1] = As[0][r0 + 8][kc + qcol];
                ah[f][2] = As[0][r0][kc + qcol + 4];
                ah[f][3] = As[0][r0 + 8][kc + qcol + 4];
                al[f][0] = As[1][r0][kc + qcol];
                al[f][1] = As[1][r0 + 8][kc + qcol];
                al[f][2] = As[1][r0][kc + qcol + 4];
                al[f][3] = As[1][r0 + 8][kc + qcol + 4];
            }
            #pragma unroll
            for (int g = 0; g < 4; g++) {
                int c0 = wn + g * 8 + qrow;
                bh[g][0] = Bs[0][c0][kc + qcol];
                bh[g][1] = Bs[0][c0][kc + qcol + 4];
                bl[g][0] = Bs[1][c0][kc + qcol];
                bl[g][1] = Bs[1][c0][kc + qcol + 4];
            }
            #pragma unroll
            for (int f = 0; f < 4; f++)
                #pragma unroll
                for (int g = 0; g < 4; g++) {
                    mma_tf32(acc[f][g], ah[f], bh[g]);
                    mma_tf32(acc[f][g], ah[f], bl[g]);
                    mma_tf32(acc[f][g], al[f], bh[g]);
                }
        }
        __syncthreads();
    }

    float* Cb = Cg + (long)b * sC;
    #pragma unroll
    for (int f = 0; f < 4; f++) {
        int r0 = m0 + wm + f * 16 + qrow;
        #pragma unroll
        for (int g = 0; g < 4; g++) {
            int cc = n0 + wn + g * 8 + qcol * 2;
            float v0 = acc[f][g][0], v1 = acc[f][g][1];
            float v2 = acc[f][g][2], v3 = acc[f][g][3];
            if (epi == 1) {
                const float* sqb = Aux + (long)b * sAux;
                v0 = sqb[cc] - 2.f * v0;
                v1 = sqb[cc + 1] - 2.f * v1;
                v2 = sqb[cc] - 2.f * v2;
                v3 = sqb[cc + 1] - 2.f * v3;
            } else if (epi == 3) {
                const float* R = Aux + (long)b * sAux;
                v0 += R[(long)r0 * Nn + cc];
                v1 += R[(long)r0 * Nn + cc + 1];
                v2 += R[(long)(r0 + 8) * Nn + cc];
                v3 += R[(long)(r0 + 8) * Nn + cc + 1];
            }
            if (epi == 2) {
                float* Hb = Cg + (long)b * sC;
                float* Lb = C2 + (long)b * sC;
                v0 = v0 >= 0.f ? v0 : 0.2f * v0;
                v1 = v1 >= 0.f ? v1 : 0.2f * v1;
                v2 = v2 >= 0.f ? v2 : 0.2f * v2;
                v3 = v3 >= 0.f ? v3 : 0.2f * v3;
                float h0 = to_tf32(v0), h1 = to_tf32(v1);
                float h2 = to_tf32(v2), h3 = to_tf32(v3);
                *reinterpret_cast<float2*>(&Hb[(long)r0 * Nn + cc]) = make_float2(h0, h1);
                *reinterpret_cast<float2*>(&Hb[(long)(r0 + 8) * Nn + cc]) = make_float2(h2, h3);
                *reinterpret_cast<float2*>(&Lb[(long)r0 * Nn + cc]) =
                    make_float2(to_tf32(v0 - h0), to_tf32(v1 - h1));
                *reinterpret_cast<float2*>(&Lb[(long)(r0 + 8) * Nn + cc]) =
                    make_float2(to_tf32(v2 - h2), to_tf32(v3 - h3));
            } else {
                *reinterpret_cast<float2*>(&Cb[(long)r0 * Nn + cc]) = make_float2(v0, v1);
                *reinterpret_cast<float2*>(&Cb[(long)(r0 + 8) * Nn + cc]) = make_float2(v2, v3);
            }
        }
    }
}

// ---------------- top-32 smallest per row: block-per-row, register-resident ----------------
// 256 threads x 16 values each. 32 rounds of block argmin; only the owning
// thread rescans its 16 registers (per-thread extraction sequence is strictly
// increasing in (value, idx), so a (exv, exi) watermark replaces a mask).
__global__ __launch_bounds__(256) void topk_kernel(const float* __restrict__ dist,
                                                   int* __restrict__ idx) {
    int row = blockIdx.x;
    const float* r = dist + (size_t)row * NPTS;
    int tid = threadIdx.x, lane = tid & 31, warp = tid >> 5;
    float v[16];
    #pragma unroll
    for (int i = 0; i < 16; i++) v[i] = r[i * 256 + tid];

    float exv = -3.4e38f;
    int exi = -1;
    float vmin = 3.4e38f;
    int gmin = 0x7fffffff;
    #pragma unroll
    for (int i = 0; i < 16; i++) {
        int g = i * 256 + tid;
        if (v[i] < vmin) { vmin = v[i]; gmin = g; }
    }

    __shared__ float swv[8];
    __shared__ int swg[8];
    __shared__ float sbv;
    __shared__ int sbg;
    int* out = idx + (size_t)row * KNB;

    for (int rr = 0; rr < KNB; rr++) {
        float wv = vmin;
        int wg = gmin;
        #pragma unroll
        for (int off = 16; off; off >>= 1) {
            float ov = __shfl_xor_sync(0xffffffffu, wv, off);
            int   og = __shfl_xor_sync(0xffffffffu, wg, off);
            if (ov < wv || (ov == wv && og < wg)) { wv = ov; wg = og; }
        }
        if (lane == 0) { swv[warp] = wv; swg[warp] = wg; }
        __syncthreads();
        if (tid == 0) {
            float bv = swv[0];
            int bg = swg[0];
            #pragma unroll
            for (int w = 1; w < 8; w++)
                if (swv[w] < bv || (swv[w] == bv && swg[w] < bg)) { bv = swv[w]; bg = swg[w]; }
            sbv = bv;
            sbg = bg;
        }
        __syncthreads();
        int bg = sbg;
        if (tid == rr) out[rr] = bg;
        if (gmin == bg) {
            exv = vmin;
            exi = gmin;
            vmin = 3.4e38f;
            gmin = 0x7fffffff;
            #pragma unroll
            for (int i = 0; i < 16; i++) {
                int g = i * 256 + tid;
                if (v[i] > exv || (v[i] == exv && g > exi)) {
                    if (v[i] < vmin || (v[i] == vmin && g < gmin)) { vmin = v[i]; gmin = g; }
                }
            }
        }
    }
}

// ---------------- fused gather + per-dim softmax attention + residual -> y1T (B,N,C) ----------------
__global__ void attn_kernel(const float* __restrict__ qT, const float* __restrict__ kT,
                            const float* __restrict__ vT, const float* __restrict__ xT,
                            const int* __restrict__ idx, float* __restrict__ y1T) {
    int b  = blockIdx.x >> 7;
    int n0 = (blockIdx.x & 127) << 5;
    int wid = threadIdx.x >> 5, lane = threadIdx.x & 31;
    const float inv = 0.17677669529663689f;  // 1/sqrt(32)
    for (int p = wid; p < 32; p += 8) {
        int n = n0 + p;
        size_t base = ((size_t)b * NPTS + n) * CH;
        float qr[4], kc[4], vc[4], o[4] = {0.f, 0.f, 0.f, 0.f};
        #pragma unroll
        for (int t = 0; t < 4; t++) {
            qr[t] = qT[base + t * 32 + lane];
            kc[t] = kT[base + t * 32 + lane];
            vc[t] = vT[base + t * 32 + lane];
        }
        int ji = idx[((size_t)b * NPTS + n) * KNB + lane];
        for (int r = 0; r < KNB; r++) {
            int j = __shfl_sync(0xffffffffu, ji, r);
            size_t jb = ((size_t)b * NPTS + j) * CH;
            #pragma unroll
            for (int t = 0; t < 4; t++) {
                float kn = kT[jb + t * 32 + lane] - kc[t];
                float vn = vT[jb + t * 32 + lane] - vc[t];
                float e = (qr[t] - kn) * inv;
                float m = e;
                #pragma unroll
                for (int off = 16; off; off >>= 1)
                    m = fmaxf(m, __shfl_xor_sync(0xffffffffu, m, off));
                float pe = __expf(e - m);
                float s = pe;
                #pragma unroll
                for (int off = 16; off; off >>= 1)
                    s += __shfl_xor_sync(0xffffffffu, s, off);
                o[t] += __fdividef(pe, s) * vn;
            }
        }
        #pragma unroll
        for (int t = 0; t < 4; t++)
            y1T[base + t * 32 + lane] = xT[base + t * 32 + lane] + o[t];
    }
}

// ---------------- BatchNorm stats on (B,N,C): stage 1 partials ----------------
__global__ void bn_part_kernel(const float* __restrict__ yT,
                               float* __restrict__ psum, float* __restrict__ psq) {
    __shared__ float s1[8][CH], s2[8][CH];
    int blk = blockIdx.x;            // 64 blocks x 256 rows
    int t = threadIdx.x;
    int c4 = (t & 31) * 4;
    int rg = t >> 5;
    float a0 = 0, a1 = 0, a2 = 0, a3 = 0, q0 = 0, q1 = 0, q2 = 0, q3 = 0;
    for (int rr = rg; rr < 256; rr += 8) {
        size_t row = (size_t)blk * 256 + rr;
        float4 v = *reinterpret_cast<const float4*>(yT + row * CH + c4);
        a0 += v.x; a1 += v.y; a2 += v.z; a3 += v.w;
        q0 += v.x * v.x; q1 += v.y * v.y; q2 += v.z * v.z; q3 += v.w * v.w;
    }
    s1[rg][c4] = a0; s1[rg][c4 + 1] = a1; s1[rg][c4 + 2] = a2; s1[rg][c4 + 3] = a3;
    s2[rg][c4] = q0; s2[rg][c4 + 1] = q1; s2[rg][c4 + 2] = q2; s2[rg][c4 + 3] = q3;
    __syncthreads();
    if (t < CH) {
        float s = 0, q = 0;
        #pragma unroll
        for (int r = 0; r < 8; r++) { s += s1[r][t]; q += s2[r][t]; }
        psum[blk * CH + t] = s;
        psq[blk * CH + t] = q;
    }
}

__global__ void bn_final_kernel(const float* __restrict__ psum, const float* __restrict__ psq,
                                float* __restrict__ mean, float* __restrict__ rstd) {
    int c = threadIdx.x;
    float s = 0, q = 0;
    for (int b = 0; b < 64; b++) { s += psum[b * CH + c]; q += psq[b * CH + c]; }
    float inv_n = 1.f / (BATCH * NPTS);
    float m = s * inv_n;
    float v = q * inv_n - m * m;
    mean[c] = m;
    rstd[c] = rsqrtf(v + BN_EPS);
}

// ---------------- BN apply on (B,N,C), optional tf32 hi/lo emit ----------------
__global__ void bn_apply_kernel(const float* __restrict__ yT,
                                const float* __restrict__ mean, const float* __restrict__ rstd,
                                const float* __restrict__ g, const float* __restrict__ bta,
                                float* __restrict__ out, float* __restrict__ ohi,
                                float* __restrict__ olo) {
    size_t i = (size_t)blockIdx.x * 256 + threadIdx.x;
    int c = (int)(i & (CH - 1));
    float y = g[c] * (yT[i] - mean[c]) * rstd[c] + bta[c];
    out[i] = y;
    if (ohi) {
        float h = to_tf32(y);
        ohi[i] = h;
        olo[i] = to_tf32(y - h);
    }
}

// ---------------- final BN apply + transpose (B,N,C) -> (B,C,N) ----------------
__global__ void bn_apply_t_kernel(const float* __restrict__ yT,
                                  const float* __restrict__ mean, const float* __restrict__ rstd,
                                  const float* __restrict__ g, const float* __restrict__ bta,
                                  float* __restrict__ out) {
    __shared__ float tile[32][33];
    int b  = blockIdx.z;
    int n0 = blockIdx.x * 32;
    int c0 = blockIdx.y * 32;
    int tx = threadIdx.x, ty = threadIdx.y;
    const float* y = yT + (size_t)b * NPTS * CH;
    #pragma unroll
    for (int i = 0; i < 32; i += 8) {
        int c = c0 + tx;
        float v = y[(size_t)(n0 + ty + i) * CH + c];
        tile[ty + i][tx] = g[c] * (v - mean[c]) * rstd[c] + bta[c];
    }
    __syncthreads();
    float* ob = out + (size_t)b * CH * NPTS;
    #pragma unroll
    for (int i = 0; i < 32; i += 8)
        ob[(size_t)(c0 + ty + i) * NPTS + n0 + tx] = tile[tx][ty + i];
}

// ---------------- host launch ----------------
extern "C" void kernel_launch(void* const* d_in, const int* in_sizes, int n_in,
                              void* d_out, int out_size) {
    const float* x  = (const float*)d_in[0];
    const float* Wq = (const float*)d_in[1];
    const float* Wk = (const float*)d_in[2];
    const float* Wv = (const float*)d_in[3];
    const float* W1 = (const float*)d_in[4];
    const float* W2 = (const float*)d_in[5];
    const float* g1 = (const float*)d_in[6];
    const float* b1 = (const float*)d_in[7];
    const float* g2 = (const float*)d_in[8];
    const float* b2 = (const float*)d_in[9];
    float* out = (float*)d_out;

    void* p;
    cudaGetSymbolAddress(&p, g_xT);   float* xT   = (float*)p;
    cudaGetSymbolAddress(&p, g_xhi);  float* xhi  = (float*)p;
    cudaGetSymbolAddress(&p, g_xlo);  float* xlo  = (float*)p;
    cudaGetSymbolAddress(&p, g_qT);   float* qT   = (float*)p;
    cudaGetSymbolAddress(&p, g_kT);   float* kT   = (float*)p;
    cudaGetSymbolAddress(&p, g_vT);   float* vT   = (float*)p;
    cudaGetSymbolAddress(&p, g_sq);   float* sq   = (float*)p;
    cudaGetSymbolAddress(&p, g_dist); float* dist = (float*)p;
    cudaGetSymbolAddress(&p, g_idx);  int*   idx  = (int*)p;
    cudaGetSymbolAddress(&p, g_y1T);  float* y1T  = (float*)p;
    cudaGetSymbolAddress(&p, g_y2T);  float* y2T  = (float*)p;
    cudaGetSymbolAddress(&p, g_y2hi); float* y2hi = (float*)p;
    cudaGetSymbolAddress(&p, g_y2lo); float* y2lo = (float*)p;
    cudaGetSymbolAddress(&p, g_hhi);  float* hhi  = (float*)p;
    cudaGetSymbolAddress(&p, g_hlo);  float* hlo  = (float*)p;
    cudaGetSymbolAddress(&p, g_y3T);  float* y3T  = (float*)p;
    cudaGetSymbolAddress(&p, g_wqhi); float* wqhi = (float*)p;
    cudaGetSymbolAddress(&p, g_wqlo); float* wqlo = (float*)p;
    cudaGetSymbolAddress(&p, g_wkhi); float* wkhi = (float*)p;
    cudaGetSymbolAddress(&p, g_wklo); float* wklo = (float*)p;
    cudaGetSymbolAddress(&p, g_wvhi); float* wvhi = (float*)p;
    cudaGetSymbolAddress(&p, g_wvlo); float* wvlo = (float*)p;
    cudaGetSymbolAddress(&p, g_w1hi); float* w1hi = (float*)p;
    cudaGetSymbolAddress(&p, g_w1lo); float* w1lo = (float*)p;
    cudaGetSymbolAddress(&p, g_w2hi); float* w2hi = (float*)p;
    cudaGetSymbolAddress(&p, g_w2lo); float* w2lo = (float*)p;
    cudaGetSymbolAddress(&p, g_psum); float* psum = (float*)p;
    cudaGetSymbolAddress(&p, g_psq);  float* psq  = (float*)p;
    cudaGetSymbolAddress(&p, g_mean); float* mean = (float*)p;
    cudaGetSymbolAddress(&p, g_rstd); float* rstd = (float*)p;

    const long NC = (long)NPTS * CH;
    const long NH = (long)NPTS * HID;
    const long NN = (long)NPTS * NPTS;

    // Launch order puts the distance MMA at position 6 so ncu (-s 5 -c 1)
    // profiles the dominant kernel.
    transpose_kernel<<<dim3(NPTS / 32, CH / 32, BATCH), dim3(32, 8)>>>(x, xT, xhi, xlo);   // 1
    sq_kernel<<<dim3(NPTS / 256, BATCH), 256>>>(x, sq);                                    // 2
    hilo_kernel<<<(CH * CH + 255) / 256, 256>>>(Wq, wqhi, wqlo, CH * CH);                  // 3
    hilo_kernel<<<(CH * CH + 255) / 256, 256>>>(Wk, wkhi, wklo, CH * CH);                  // 4
    hilo_kernel<<<(CH * CH + 255) / 256, 256>>>(Wv, wvhi, wvlo, CH * CH);                  // 5

    // distance (ranking-equivalent): dist[i][j] = sq[j] - 2 <x_i, x_j>      // 6 (profiled)
    mma_nt_kernel<<<dim3(NPTS / 128, NPTS / 128, BATCH), 256>>>(xhi, xlo, xhi, xlo, dist, nullptr,
        sq, NPTS, NPTS, CH, 1, NC, NC, NN, NPTS);

    topk_kernel<<<BATCH * NPTS, 256>>>(dist, idx);

    hilo_kernel<<<(HID * CH + 255) / 256, 256>>>(W1, w1hi, w1lo, HID * CH);
    hilo_kernel<<<(CH * HID + 255) / 256, 256>>>(W2, w2hi, w2lo, CH * HID);

    // projections: (NPTS x CH) = xT (NPTS x CH) * W^T
    mma_nt_kernel<<<dim3(1, NPTS / 128, BATCH), 256>>>(xhi, xlo, wqhi, wqlo, qT, nullptr,
        nullptr, NPTS, CH, CH, 0, NC, 0, NC, 0);
    mma_nt_kernel<<<dim3(1, NPTS / 128, BATCH), 256>>>(xhi, xlo, wkhi, wklo, kT, nullptr,
        nullptr, NPTS, CH, CH, 0, NC, 0, NC, 0);
    mma_nt_kernel<<<dim3(1, NPTS / 128, BATCH), 256>>>(xhi, xlo, wvhi, wvlo, vT, nullptr,
        nullptr, NPTS, CH, CH, 0, NC, 0, NC, 0);

    attn_kernel<<<BATCH * NPTS / 32, 256>>>(qT, kT, vT, xT, idx, y1T);

    bn_part_kernel<<<64, 256>>>(y1T, psum, psq);
    bn_final_kernel<<<1, CH>>>(psum, psq, mean, rstd);
    bn_apply_kernel<<<(int)(BATCH * NC / 256), 256>>>(y1T, mean, rstd, g1, b1, y2T, y2hi, y2lo);

    // FFN: hT = leaky(y2T * W1^T) (hi/lo); y3T = hT * W2^T + y2T
    mma_nt_kernel<<<dim3(HID / 128, NPTS / 128, BATCH), 256>>>(y2hi, y2lo, w1hi, w1lo, hhi, hlo,
        nullptr, NPTS, HID, CH, 2, NC, 0, NH, 0);
    mma_nt_kernel<<<dim3(1, NPTS / 128, BATCH), 256>>>(hhi, hlo, w2hi, w2lo, y3T, nullptr,
        y2T, NPTS, CH, HID, 3, NH, 0, NC, NC);

    bn_part_kernel<<<64, 256>>>(y3T, psum, psq);
    bn_final_kernel<<<1, CH>>>(psum, psq, mean, rstd);
    bn_apply_t_kernel<<<dim3(NPTS / 32, CH / 32, BATCH), dim3(32, 8)>>>(y3T, mean, rstd, g2, b2, out);
}